// round 11
// baseline (speedup 1.0000x reference)
#include <cuda_runtime.h>
#include <cuda_bf16.h>
#include <math.h>
#include <stdint.h>

#define S_    4
#define N_    10000
#define NP_   10048
#define L_    8
#define F_    128
#define G3_   384
#define OR_   64
#define SUB_  100
#define SEQ_  (S_*N_)
#define SEQP  40064                // padded rows for g_yw2 (313*128)
#define MB_   64
#define NT_   256
#define MB2_  128
#define NT2_  512
#define TILES_ (SEQ_/MB_)          // 625 (gru1)
#define T2_    313                 // gru2 tiles (128 rows each)
#define PTILES_ (NP_/MB_)          // 157
#define NB_LOSS (S_*SUB_*(L_-1))
#define LOSS_CNT 179200.0f
#define APITCH 264
#define BPITCH 136
#define CHUNKE (128*BPITCH)

__device__ int      g_walksf[SEQ_*L_];
__device__ unsigned g_upk[SEQ_];
__device__ float    g_wg[8*G3_];
__device__ float    g_P[N_*G3_];
__device__ __nv_bfloat16 g_h2[(size_t)NP_*256];
__device__ __nv_bfloat16 g_yw2[(size_t)L_*SEQP*256];   // GRU1 out split (hi|lo), padded
__device__ float    g_yseq[L_-1][SEQ_*F_];
__device__ float    g_part1[NB_LOSS];
__device__ float    g_part2[NB_LOSS];
__device__ float    g_posw;
__device__ __nv_bfloat16 g_W1h[G3_*F_], g_W1l[G3_*F_];
__device__ __nv_bfloat16 g_W2h[G3_*F_], g_W2l[G3_*F_];
__device__ __nv_bfloat16 g_WXh[G3_*F_], g_WXl[G3_*F_];
__device__ __nv_bfloat16 g_WAh[G3_*F_], g_WAl[G3_*F_];

__device__ __forceinline__ float sigf(float x) { return __fdividef(1.f, 1.f + __expf(-x)); }
__device__ __forceinline__ float tanh_s(float x) {
    float ax = fabsf(x); float e = __expf(-2.f*ax);
    return copysignf(__fdividef(1.f - e, 1.f + e), x);
}
__device__ __forceinline__ float softplusf(float x) {
    return fmaxf(x, 0.f) + log1pf(__expf(-fabsf(x)));
}
__device__ __forceinline__ float2 unpackbf(uint32_t u) {
    __nv_bfloat162 v = *(__nv_bfloat162*)&u;
    return make_float2(__bfloat162float(v.x), __bfloat162float(v.y));
}

__device__ __forceinline__ void mma16816(float c[4], uint32_t a0, uint32_t a1,
                                         uint32_t a2, uint32_t a3, uint32_t b0, uint32_t b1) {
    asm volatile("mma.sync.aligned.m16n8k16.row.col.f32.bf16.bf16.f32 "
                 "{%0,%1,%2,%3}, {%4,%5,%6,%7}, {%8,%9}, {%0,%1,%2,%3};\n"
                 : "+f"(c[0]), "+f"(c[1]), "+f"(c[2]), "+f"(c[3])
                 : "r"(a0), "r"(a1), "r"(a2), "r"(a3), "r"(b0), "r"(b1));
}
__device__ __forceinline__ void ldsm_x4(uint32_t& r0, uint32_t& r1, uint32_t& r2, uint32_t& r3,
                                        const void* p) {
    uint32_t a = (uint32_t)__cvta_generic_to_shared(p);
    asm volatile("ldmatrix.sync.aligned.m8n8.x4.shared.b16 {%0,%1,%2,%3}, [%4];"
                 : "=r"(r0), "=r"(r1), "=r"(r2), "=r"(r3) : "r"(a));
}

// 3-segment pair GEMM (GRU1)
__device__ __forceinline__ void run_gemm(float (&acc)[2][4][4],
    const __nv_bfloat16* __restrict__ A, const __nv_bfloat16* __restrict__ B,
    int lane, int wc)
{
    const int rl = lane & 15;
    const int kp = (lane >> 4) << 3;
#pragma unroll
    for (int ks = 0; ks < 8; ks++) {
        const int k0 = ks*16 + kp;
        uint32_t ah[2][4], al[2][4];
#pragma unroll
        for (int mt = 0; mt < 2; mt++) {
            const __nv_bfloat16* Ar = A + (mt*16 + rl)*APITCH + k0;
            ldsm_x4(ah[mt][0], ah[mt][1], ah[mt][2], ah[mt][3], Ar);
            ldsm_x4(al[mt][0], al[mt][1], al[mt][2], al[mt][3], Ar + 128);
        }
#pragma unroll
        for (int np = 0; np < 2; np++) {
            const __nv_bfloat16* Br = B + (wc*32 + np*16 + rl)*BPITCH + k0;
            uint32_t bh[4], bl[4];
            ldsm_x4(bh[0], bh[1], bh[2], bh[3], Br);
            ldsm_x4(bl[0], bl[1], bl[2], bl[3], Br + CHUNKE);
#pragma unroll
            for (int mt = 0; mt < 2; mt++) {
                mma16816(acc[mt][np*2+0], ah[mt][0], ah[mt][1], ah[mt][2], ah[mt][3], bh[0], bh[2]);
                mma16816(acc[mt][np*2+1], ah[mt][0], ah[mt][1], ah[mt][2], ah[mt][3], bh[1], bh[3]);
                mma16816(acc[mt][np*2+0], al[mt][0], al[mt][1], al[mt][2], al[mt][3], bh[0], bh[2]);
                mma16816(acc[mt][np*2+1], al[mt][0], al[mt][1], al[mt][2], al[mt][3], bh[1], bh[3]);
                mma16816(acc[mt][np*2+0], ah[mt][0], ah[mt][1], ah[mt][2], ah[mt][3], bl[0], bl[2]);
                mma16816(acc[mt][np*2+1], ah[mt][0], ah[mt][1], ah[mt][2], ah[mt][3], bl[1], bl[3]);
            }
        }
    }
}

// single-chunk GEMMs
template<int WITH_LO>
__device__ __forceinline__ void run_seg(float (&acc)[2][4][4],
    const __nv_bfloat16* __restrict__ A, const __nv_bfloat16* __restrict__ W,
    int lane, int wc)
{
    const int rl = lane & 15;
    const int kp = (lane >> 4) << 3;
#pragma unroll
    for (int ks = 0; ks < 8; ks++) {
        const int k0 = ks*16 + kp;
        uint32_t ah[2][4], al[2][4];
#pragma unroll
        for (int mt = 0; mt < 2; mt++) {
            const __nv_bfloat16* Ar = A + (mt*16 + rl)*APITCH + k0;
            ldsm_x4(ah[mt][0], ah[mt][1], ah[mt][2], ah[mt][3], Ar);
            if (WITH_LO) ldsm_x4(al[mt][0], al[mt][1], al[mt][2], al[mt][3], Ar + 128);
        }
#pragma unroll
        for (int np = 0; np < 2; np++) {
            const __nv_bfloat16* Wr = W + (wc*32 + np*16 + rl)*BPITCH + k0;
            uint32_t bh[4];
            ldsm_x4(bh[0], bh[1], bh[2], bh[3], Wr);
#pragma unroll
            for (int mt = 0; mt < 2; mt++) {
                mma16816(acc[mt][np*2+0], ah[mt][0], ah[mt][1], ah[mt][2], ah[mt][3], bh[0], bh[2]);
                mma16816(acc[mt][np*2+1], ah[mt][0], ah[mt][1], ah[mt][2], ah[mt][3], bh[1], bh[3]);
                if (WITH_LO) {
                    mma16816(acc[mt][np*2+0], al[mt][0], al[mt][1], al[mt][2], al[mt][3], bh[0], bh[2]);
                    mma16816(acc[mt][np*2+1], al[mt][0], al[mt][1], al[mt][2], al[mt][3], bh[1], bh[3]);
                }
            }
        }
    }
}

// GRU1 sync pair staging (NT_=256)
__device__ __forceinline__ void stage_pair(__nv_bfloat16* dst,
    const __nv_bfloat16* __restrict__ hi, const __nv_bfloat16* __restrict__ lo,
    int jg, int tid)
{
    const __nv_bfloat16* s0 = hi + (size_t)jg*128*128;
    const __nv_bfloat16* s1 = lo + (size_t)jg*128*128;
#pragma unroll
    for (int it = 0; it < 8; it++) {
        int i = tid + it*NT_;
        int row = i >> 4, seg = (i & 15) << 3;
        *(uint4*)(dst + row*BPITCH + seg)          = *(const uint4*)(s0 + row*128 + seg);
        *(uint4*)(dst + CHUNKE + row*BPITCH + seg) = *(const uint4*)(s1 + row*128 + seg);
    }
}

__device__ __forceinline__ void cpa16(uint32_t d, const void* s) {
    asm volatile("cp.async.cg.shared.global [%0], [%1], 16;\n" :: "r"(d), "l"(s));
}
// pT single-chunk staging (NT_=256)
__device__ __forceinline__ void stage1(uint32_t dstB, const __nv_bfloat16* __restrict__ src,
                                       int tid)
{
#pragma unroll
    for (int it = 0; it < 8; it++) {
        int i = tid + it*NT_;
        int row = i >> 4, seg = (i & 15) << 3;
        cpa16(dstB + (uint32_t)(row*BPITCH + seg)*2u, src + row*128 + seg);
    }
}
__device__ __forceinline__ void cp_wait_all() {
    asm volatile("cp.async.commit_group;\n");
    asm volatile("cp.async.wait_group 0;\n" ::: "memory");
}

// GRU2 staging (NT2_=512) + double-buffer phase
__device__ __forceinline__ void stage512(uint32_t dstB, const __nv_bfloat16* __restrict__ src,
                                         int tid)
{
#pragma unroll
    for (int it = 0; it < 4; it++) {
        int i = tid + it*NT2_;
        int row = i >> 4, seg = (i & 15) << 3;
        cpa16(dstB + (uint32_t)(row*BPITCH + seg)*2u, src + row*128 + seg);
    }
}
__device__ __forceinline__ void phase512(uint32_t dnext, const __nv_bfloat16* __restrict__ nsrc,
                                         int tid)
{
    __syncthreads();                      // prior run done -> next buffer free
    stage512(dnext, nsrc, tid);
    asm volatile("cp.async.commit_group;\n");
    asm volatile("cp.async.wait_group 1;\n" ::: "memory");   // current chunk landed
    __syncthreads();
}

// GRU1 gi loader
__device__ __forceinline__ void load_gi1(float (&acc)[2][4][4], int jg, int t,
    const int* __restrict__ sh_i, const float* __restrict__ sh_bh, int addbias,
    int rbase, int g, int tg2, int wc)
{
#pragma unroll
    for (int mt = 0; mt < 2; mt++) {
        int u0 = (sh_i[rbase + mt*16 + g]     >> (4*t)) & 7;
        int u1 = (sh_i[rbase + mt*16 + g + 8] >> (4*t)) & 7;
#pragma unroll
        for (int nt = 0; nt < 4; nt++) {
            int cc = jg*F_ + wc*32 + nt*8 + tg2;
            float2 p0 = *(const float2*)&g_wg[u0*G3_ + cc];
            float2 p1 = *(const float2*)&g_wg[u1*G3_ + cc];
            acc[mt][nt][0]=p0.x; acc[mt][nt][1]=p0.y; acc[mt][nt][2]=p1.x; acc[mt][nt][3]=p1.y;
            if (addbias) {
                float2 bh = *(const float2*)&sh_bh[cc];
                acc[mt][nt][0]+=bh.x; acc[mt][nt][1]+=bh.y; acc[mt][nt][2]+=bh.x; acc[mt][nt][3]+=bh.y;
            }
        }
    }
}

// GRU2 gi loader (P gather)
__device__ __forceinline__ void load_gi2(float (&acc)[2][4][4], int jg,
    const int* __restrict__ sh_i, const float* __restrict__ sh_bh, int addbias,
    int rbase, int g, int tg2, int wc)
{
#pragma unroll
    for (int mt = 0; mt < 2; mt++) {
        int i0 = sh_i[rbase + mt*16 + g], i1 = sh_i[rbase + mt*16 + g + 8];
#pragma unroll
        for (int nt = 0; nt < 4; nt++) {
            int cc = jg*F_ + wc*32 + nt*8 + tg2;
            float2 p0 = *(const float2*)&g_P[(size_t)i0*G3_ + cc];
            float2 p1 = *(const float2*)&g_P[(size_t)i1*G3_ + cc];
            acc[mt][nt][0]=p0.x; acc[mt][nt][1]=p0.y; acc[mt][nt][2]=p1.x; acc[mt][nt][3]=p1.y;
            if (addbias) {
                float2 bh = *(const float2*)&sh_bh[cc];
                acc[mt][nt][0]+=bh.x; acc[mt][nt][1]+=bh.y; acc[mt][nt][2]+=bh.x; acc[mt][nt][3]+=bh.y;
            }
        }
    }
}

// ---------------- preprocessing ----------------
__global__ void prep_kernel(const int* __restrict__ walks)
{
    int m = blockIdx.x * blockDim.x + threadIdx.x;
    if (m >= SEQ_) return;
    int w[L_];
#pragma unroll
    for (int p = 0; p < L_; p++) w[p] = walks[m*L_ + p];
    unsigned pk = 0;
#pragma unroll
    for (int t = 0; t < L_; t++) {
        int p = L_-1-t, wp = w[p], u = p;
#pragma unroll
        for (int q = L_-1; q >= 0; q--) if (w[q] == wp) u = q;
        g_walksf[m*L_ + t] = wp;
        pk |= ((unsigned)u) << (4*t);
    }
    g_upk[m] = pk;
}

__global__ void wg_kernel(const float* __restrict__ Wih_w, const float* __restrict__ bih_w)
{
    int j = threadIdx.x;
    float b = bih_w[j];
#pragma unroll
    for (int u = 0; u < 8; u++) g_wg[u*G3_ + j] = Wih_w[j*8 + u] + b;
}

__global__ void pack_kernel(const float* __restrict__ Whh_w, const float* __restrict__ Whh,
                            const float* __restrict__ Wih)
{
    int i = blockIdx.x * 256 + threadIdx.x;
    if (i >= G3_*F_) return;
    float a = Whh_w[i];
    __nv_bfloat16 h1 = __float2bfloat16(a);
    g_W1h[i] = h1; g_W1l[i] = __float2bfloat16(a - __bfloat162float(h1));
    float b = Whh[i];
    __nv_bfloat16 h2 = __float2bfloat16(b);
    g_W2h[i] = h2; g_W2l[i] = __float2bfloat16(b - __bfloat162float(h2));
    int n = i >> 7, k = i & 127;
    float c = Wih[n*256 + 128 + k];
    __nv_bfloat16 h3 = __float2bfloat16(c);
    g_WXh[i] = h3; g_WXl[i] = __float2bfloat16(c - __bfloat162float(h3));
    float d = Wih[n*256 + k];
    __nv_bfloat16 h4 = __float2bfloat16(d);
    g_WAh[i] = h4; g_WAl[i] = __float2bfloat16(d - __bfloat162float(h4));
}

__global__ void packh_kernel(const float* __restrict__ h)
{
    int i = blockIdx.x * 256 + threadIdx.x;
    if (i >= NP_*F_) return;
    int n = i >> 7, k = i & 127;
    float v = (n < N_) ? h[(size_t)n*F_ + k] : 0.f;
    __nv_bfloat16 hi = __float2bfloat16(v);
    g_h2[(size_t)n*256 + k]       = hi;
    g_h2[(size_t)n*256 + 128 + k] = __float2bfloat16(v - __bfloat162float(hi));
}

// ---------------- P = h @ WihA^T + bih (tensor cores) ----------------
__global__ void __launch_bounds__(NT_) pT_kernel(const float* __restrict__ bih)
{
    extern __shared__ char smc[];
    __nv_bfloat16* sh_x2 = (__nv_bfloat16*)smc;            // 33792
    __nv_bfloat16* sh_W  = (__nv_bfloat16*)(smc + 33792);  // 34816

    const int tid = threadIdx.x, wid = tid >> 5, lane = tid & 31;
    const int wr = wid & 1, wc = wid >> 1;
    const int g = lane >> 2, tg2 = (lane & 3)*2;
    const int rbase = wr*32;
    const int m0 = blockIdx.x*MB_, jg = blockIdx.y;
    const uint32_t sWu = (uint32_t)__cvta_generic_to_shared(sh_W);

#pragma unroll
    for (int it = 0; it < 8; it++) {
        int i = tid + it*NT_;
        int row = i >> 5, seg = (i & 31) << 3;
        *(uint4*)(sh_x2 + row*APITCH + seg) =
            *(const uint4*)(g_h2 + ((size_t)(m0 + row))*256 + seg);
    }
    stage1(sWu, g_WAh + (size_t)jg*16384, tid);
    cp_wait_all();
    __syncthreads();

    float acc[2][4][4];
#pragma unroll
    for (int mt = 0; mt < 2; mt++)
#pragma unroll
        for (int nt = 0; nt < 4; nt++) {
            int cc = jg*F_ + wc*32 + nt*8 + tg2;
            float2 b = *(const float2*)&bih[cc];
            acc[mt][nt][0]=b.x; acc[mt][nt][1]=b.y; acc[mt][nt][2]=b.x; acc[mt][nt][3]=b.y;
        }
    run_seg<1>(acc, sh_x2 + rbase*APITCH, sh_W, lane, wc);
    __syncthreads();
    stage1(sWu, g_WAl + (size_t)jg*16384, tid);
    cp_wait_all();
    __syncthreads();
    run_seg<0>(acc, sh_x2 + rbase*APITCH, sh_W, lane, wc);

#pragma unroll
    for (int mt = 0; mt < 2; mt++)
#pragma unroll
        for (int nt = 0; nt < 4; nt++) {
            int cc = jg*F_ + wc*32 + nt*8 + tg2;
#pragma unroll
            for (int p2 = 0; p2 < 2; p2++) {
                int n = m0 + rbase + mt*16 + g + p2*8;
                if (n < N_)
                    *(float2*)&g_P[(size_t)n*G3_ + cc] =
                        make_float2(acc[mt][nt][p2*2], acc[mt][nt][p2*2+1]);
            }
        }
}

// ---------------- GRU1 (2 blocks/SM, SEQP output stride) ----------------
__global__ void __launch_bounds__(NT_, 2) gru1_kernel(const float* __restrict__ bhh)
{
    extern __shared__ char smc[];
    __nv_bfloat16* sh_h2 = (__nv_bfloat16*)smc;                  // 33792
    __nv_bfloat16* sh_B  = (__nv_bfloat16*)(smc + 33792);        // 69632
    float* sh_bh = (float*)(smc + 33792 + 69632);
    int*   sh_i  = (int*)(sh_bh + G3_);

    const int tid = threadIdx.x, wid = tid >> 5, lane = tid & 31;
    const int wr = wid & 1, wc = wid >> 1;
    const int g = lane >> 2, tg2 = (lane & 3)*2;
    const int rbase = wr*32;
    const int m0 = blockIdx.x*MB_;

    for (int i = tid; i < G3_; i += NT_) sh_bh[i] = bhh[i];
    for (int i = tid; i < MB_*APITCH/2; i += NT_) ((uint32_t*)sh_h2)[i] = 0u;
    if (tid < MB_) sh_i[tid] = (int)g_upk[m0 + tid];

#pragma unroll 1
    for (int t = 0; t < L_; t++) {
        const bool doH = (t > 0);
        float nn[2][4][4];
        {
            float rr[2][4][4];
            __syncthreads();
            if (doH) stage_pair(sh_B, g_W1h, g_W1l, 0, tid);
            __syncthreads();
            load_gi1(rr, 0, t, sh_i, sh_bh, 1, rbase, g, tg2, wc);
            if (doH) run_gemm(rr, sh_h2 + rbase*APITCH, sh_B, lane, wc);
#pragma unroll
            for (int mt=0; mt<2; mt++)
#pragma unroll
                for (int nt=0; nt<4; nt++)
#pragma unroll
                    for (int q=0; q<4; q++) rr[mt][nt][q] = sigf(rr[mt][nt][q]);

            __syncthreads();
            if (doH) stage_pair(sh_B, g_W1h, g_W1l, 2, tid);
            __syncthreads();
            float acci[2][4][4], acch[2][4][4];
            load_gi1(acci, 2, t, sh_i, nullptr, 0, rbase, g, tg2, wc);
#pragma unroll
            for (int mt=0; mt<2; mt++)
#pragma unroll
                for (int nt=0; nt<4; nt++) {
                    int cc = 2*F_ + wc*32 + nt*8 + tg2;
                    float2 bh = *(const float2*)&sh_bh[cc];
                    acch[mt][nt][0]=bh.x; acch[mt][nt][1]=bh.y;
                    acch[mt][nt][2]=bh.x; acch[mt][nt][3]=bh.y;
                }
            if (doH) run_gemm(acch, sh_h2 + rbase*APITCH, sh_B, lane, wc);
#pragma unroll
            for (int mt=0; mt<2; mt++)
#pragma unroll
                for (int nt=0; nt<4; nt++)
#pragma unroll
                    for (int q=0; q<4; q++)
                        nn[mt][nt][q] = tanh_s(acci[mt][nt][q] + rr[mt][nt][q]*acch[mt][nt][q]);
        }

        float zz[2][4][4];
        __syncthreads();
        if (doH) stage_pair(sh_B, g_W1h, g_W1l, 1, tid);
        __syncthreads();
        load_gi1(zz, 1, t, sh_i, sh_bh, 1, rbase, g, tg2, wc);
        if (doH) run_gemm(zz, sh_h2 + rbase*APITCH, sh_B, lane, wc);
#pragma unroll
        for (int mt=0; mt<2; mt++)
#pragma unroll
            for (int nt=0; nt<4; nt++)
#pragma unroll
                for (int q=0; q<4; q++) zz[mt][nt][q] = sigf(zz[mt][nt][q]);

        __syncthreads();
#pragma unroll
        for (int mt=0; mt<2; mt++)
#pragma unroll
            for (int nt=0; nt<4; nt++) {
                int cc = wc*32 + nt*8 + tg2;
#pragma unroll
                for (int p2=0; p2<2; p2++) {
                    int r = rbase + mt*16 + g + p2*8;
                    float n0 = nn[mt][nt][p2*2], n1 = nn[mt][nt][p2*2+1];
                    float z0 = zz[mt][nt][p2*2], z1 = zz[mt][nt][p2*2+1];
                    float2 hh = unpackbf(*(uint32_t*)&sh_h2[r*APITCH + cc]);
                    float2 hl = unpackbf(*(uint32_t*)&sh_h2[r*APITCH + 128 + cc]);
                    float h0 = (1.f - z0)*n0 + z0*(hh.x + hl.x);
                    float h1 = (1.f - z1)*n1 + z1*(hh.y + hl.y);
                    __nv_bfloat16 s0 = __float2bfloat16(h0), s1 = __float2bfloat16(h1);
                    __nv_bfloat162 hv; hv.x = s0; hv.y = s1;
                    uint32_t hiv = *(uint32_t*)&hv;
                    __nv_bfloat162 lv = __floats2bfloat162_rn(h0 - __bfloat162float(s0),
                                                              h1 - __bfloat162float(s1));
                    uint32_t lov = *(uint32_t*)&lv;
                    *(uint32_t*)&sh_h2[r*APITCH + cc] = hiv;
                    *(uint32_t*)&sh_h2[r*APITCH + 128 + cc] = lov;
                    size_t base = ((size_t)t*SEQP + m0 + r)*256 + cc;
                    *(uint32_t*)&g_yw2[base]       = hiv;
                    *(uint32_t*)&g_yw2[base + 128] = lov;
                }
            }
    }
}

// ---------------- GRU2: MB=128, NT=512, double-buffered weights ----------------
__global__ void __launch_bounds__(NT2_, 1) gru2_kernel(const float* __restrict__ bhh,
                                                       float* __restrict__ hT_out)
{
    extern __shared__ char smc[];
    __nv_bfloat16* sh_h2 = (__nv_bfloat16*)smc;                  // 67584
    __nv_bfloat16* sh_x2 = (__nv_bfloat16*)(smc + 67584);        // 67584
    __nv_bfloat16* sh_W0 = (__nv_bfloat16*)(smc + 135168);       // 34816
    __nv_bfloat16* sh_W1 = (__nv_bfloat16*)(smc + 169984);       // 34816
    float* sh_bh = (float*)(smc + 204800);                       // 1536
    int*   sh_i  = (int*)(smc + 206336);                         // 512

    const int tid = threadIdx.x, wid = tid >> 5, lane = tid & 31;
    const int wr = wid & 3, wc = wid >> 2;       // 4 row-warps x 4 col-warps
    const int g = lane >> 2, tg2 = (lane & 3)*2;
    const int rbase = wr*32;
    const int m0 = blockIdx.x*MB2_;
    const uint32_t b0u = (uint32_t)__cvta_generic_to_shared(sh_W0);
    const uint32_t b1u = (uint32_t)__cvta_generic_to_shared(sh_W1);

    for (int i = tid; i < G3_; i += NT2_) sh_bh[i] = bhh[i];
#pragma unroll
    for (int it = 0; it < 8; it++) {
        int i = tid + it*NT2_;
        int row = i >> 5, seg = (i & 31) << 3;
        *(uint4*)(sh_h2 + row*APITCH + seg) =
            *(const uint4*)(g_yw2 + ((size_t)(L_-1)*SEQP + m0 + row)*256 + seg);
    }
    // prologue: chunk C0 (WXh gate r) into buf0
    stage512(b0u, g_WXh, tid);
    asm volatile("cp.async.commit_group;\n");

#pragma unroll 1
    for (int t = 0; t < L_; t++) {
        // x tile + node indices for this step (visibility via first phase syncs)
#pragma unroll
        for (int it = 0; it < 8; it++) {
            int i = tid + it*NT2_;
            int row = i >> 5, seg = (i & 31) << 3;
            *(uint4*)(sh_x2 + row*APITCH + seg) =
                *(const uint4*)(g_yw2 + ((size_t)t*SEQP + m0 + row)*256 + seg);
        }
        if (tid < MB2_) {
            int mr = m0 + tid;
            sh_i[tid] = (mr < SEQ_) ? g_walksf[(size_t)mr*L_ + t] : 0;
        }

        float nn[2][4][4];
        {
            // ---- gate r (jg=0): C0=WXh,C1=WXl,C2=W2h,C3=W2l ----
            float rr[2][4][4];
            phase512(b1u, g_WXl, tid);                       // wait C0, prefetch C1
            load_gi2(rr, 0, sh_i, sh_bh, 1, rbase, g, tg2, wc);
            run_seg<1>(rr, sh_x2 + rbase*APITCH, sh_W0, lane, wc);
            phase512(b0u, g_W2h, tid);                       // wait C1, prefetch C2
            run_seg<0>(rr, sh_x2 + rbase*APITCH, sh_W1, lane, wc);
            phase512(b1u, g_W2l, tid);                       // wait C2, prefetch C3
            run_seg<1>(rr, sh_h2 + rbase*APITCH, sh_W0, lane, wc);
            phase512(b0u, g_WXh + 2*16384, tid);             // wait C3, prefetch C4
            run_seg<0>(rr, sh_h2 + rbase*APITCH, sh_W1, lane, wc);
#pragma unroll
            for (int mt=0; mt<2; mt++)
#pragma unroll
                for (int nt=0; nt<4; nt++)
#pragma unroll
                    for (int q=0; q<4; q++) rr[mt][nt][q] = sigf(rr[mt][nt][q]);

            // ---- gate n (jg=2): C4..C7 ----
            float acci[2][4][4], acch[2][4][4];
            phase512(b1u, g_WXl + 2*16384, tid);             // wait C4, prefetch C5
            load_gi2(acci, 2, sh_i, nullptr, 0, rbase, g, tg2, wc);
#pragma unroll
            for (int mt=0; mt<2; mt++)
#pragma unroll
                for (int nt=0; nt<4; nt++) {
                    int cc = 2*F_ + wc*32 + nt*8 + tg2;
                    float2 bh = *(const float2*)&sh_bh[cc];
                    acch[mt][nt][0]=bh.x; acch[mt][nt][1]=bh.y;
                    acch[mt][nt][2]=bh.x; acch[mt][nt][3]=bh.y;
                }
            run_seg<1>(acci, sh_x2 + rbase*APITCH, sh_W0, lane, wc);
            phase512(b0u, g_W2h + 2*16384, tid);             // wait C5, prefetch C6
            run_seg<0>(acci, sh_x2 + rbase*APITCH, sh_W1, lane, wc);
            phase512(b1u, g_W2l + 2*16384, tid);             // wait C6, prefetch C7
            run_seg<1>(acch, sh_h2 + rbase*APITCH, sh_W0, lane, wc);
            phase512(b0u, g_WXh + 1*16384, tid);             // wait C7, prefetch C8
            run_seg<0>(acch, sh_h2 + rbase*APITCH, sh_W1, lane, wc);
#pragma unroll
            for (int mt=0; mt<2; mt++)
#pragma unroll
                for (int nt=0; nt<4; nt++)
#pragma unroll
                    for (int q=0; q<4; q++)
                        nn[mt][nt][q] = tanh_s(acci[mt][nt][q] + rr[mt][nt][q]*acch[mt][nt][q]);
        }

        // ---- gate z (jg=1): C8..C11 ----
        float zz[2][4][4];
        phase512(b1u, g_WXl + 1*16384, tid);                 // wait C8, prefetch C9
        load_gi2(zz, 1, sh_i, sh_bh, 1, rbase, g, tg2, wc);
        run_seg<1>(zz, sh_x2 + rbase*APITCH, sh_W0, lane, wc);
        phase512(b0u, g_W2h + 1*16384, tid);                 // wait C9, prefetch C10
        run_seg<0>(zz, sh_x2 + rbase*APITCH, sh_W1, lane, wc);
        phase512(b1u, g_W2l + 1*16384, tid);                 // wait C10, prefetch C11
        run_seg<1>(zz, sh_h2 + rbase*APITCH, sh_W0, lane, wc);
        phase512(b0u, g_WXh, tid);                           // wait C11, prefetch next C0
        run_seg<0>(zz, sh_h2 + rbase*APITCH, sh_W1, lane, wc);
#pragma unroll
        for (int mt=0; mt<2; mt++)
#pragma unroll
            for (int nt=0; nt<4; nt++)
#pragma unroll
                for (int q=0; q<4; q++) zz[mt][nt][q] = sigf(zz[mt][nt][q]);

        __syncthreads();   // all h-GEMM reads complete before h update
#pragma unroll
        for (int mt=0; mt<2; mt++)
#pragma unroll
            for (int nt=0; nt<4; nt++) {
                int cc = wc*32 + nt*8 + tg2;
#pragma unroll
                for (int p2=0; p2<2; p2++) {
                    int r = rbase + mt*16 + g + p2*8;
                    float n0 = nn[mt][nt][p2*2], n1 = nn[mt][nt][p2*2+1];
                    float z0 = zz[mt][nt][p2*2], z1 = zz[mt][nt][p2*2+1];
                    float2 hh = unpackbf(*(uint32_t*)&sh_h2[r*APITCH + cc]);
                    float2 hl = unpackbf(*(uint32_t*)&sh_h2[r*APITCH + 128 + cc]);
                    float h0 = (1.f - z0)*n0 + z0*(hh.x + hl.x);
                    float h1 = (1.f - z1)*n1 + z1*(hh.y + hl.y);
                    __nv_bfloat16 s0 = __float2bfloat16(h0), s1 = __float2bfloat16(h1);
                    __nv_bfloat162 hv; hv.x = s0; hv.y = s1;
                    uint32_t hiv = *(uint32_t*)&hv;
                    __nv_bfloat162 lv = __floats2bfloat162_rn(h0 - __bfloat162float(s0),
                                                              h1 - __bfloat162float(s1));
                    uint32_t lov = *(uint32_t*)&lv;
                    *(uint32_t*)&sh_h2[r*APITCH + cc] = hiv;
                    *(uint32_t*)&sh_h2[r*APITCH + 128 + cc] = lov;
                    int mr = m0 + r;
                    if (mr < SEQ_) {
                        float* dst = (t < L_-1) ? (g_yseq[t] + (size_t)mr*F_ + cc)
                                                : (hT_out   + (size_t)mr*F_ + cc);
                        *(float2*)dst = make_float2(h0, h1);
                    }
                }
            }
        __syncthreads();   // h update visible before next step's reads
    }
}

// ---------------- loss ----------------
__global__ void lsum_kernel(const int* __restrict__ idxs, const float* __restrict__ y0)
{
    int b = blockIdx.x;
    int t = b % (L_-1), j = (b/(L_-1)) % SUB_, s = b/((L_-1)*SUB_);
    int seq = s*N_ + idxs[j];
    int node = g_walksf[(size_t)seq*L_ + t + 1];
    int o = threadIdx.x;
    __shared__ float red[OR_];
    red[o] = y0[(size_t)node*OR_ + o]; __syncthreads();
    for (int st = OR_/2; st > 0; st >>= 1) { if (o < st) red[o] += red[o+st]; __syncthreads(); }
    if (o == 0) g_part1[b] = red[0];
}

__global__ void lred1_kernel()
{
    __shared__ float red[256];
    int tid = threadIdx.x; float s = 0.f;
    for (int i = tid; i < NB_LOSS; i += 256) s += g_part1[i];
    red[tid] = s; __syncthreads();
    for (int st = 128; st > 0; st >>= 1) { if (tid < st) red[tid] += red[tid+st]; __syncthreads(); }
    if (tid == 0) g_posw = LOSS_CNT / red[0];
}

__global__ void lbce_kernel(const int* __restrict__ idxs, const float* __restrict__ y0,
                            const float* __restrict__ Wss, const float* __restrict__ bss)
{
    int b = blockIdx.x;
    int t = b % (L_-1), j = (b/(L_-1)) % SUB_, s = b/((L_-1)*SUB_);
    int seq = s*N_ + idxs[j];
    __shared__ float yrow[F_];
    int o = threadIdx.x;
    yrow[o]      = g_yseq[t][(size_t)seq*F_ + o];
    yrow[o + 64] = g_yseq[t][(size_t)seq*F_ + o + 64];
    __syncthreads();
    float acc = bss[o];
    const float4* wrp = (const float4*)(Wss + (size_t)o*F_);
#pragma unroll 8
    for (int k = 0; k < F_/4; k++) {
        float4 w = wrp[k];
        acc += yrow[k*4]*w.x + yrow[k*4+1]*w.y + yrow[k*4+2]*w.z + yrow[k*4+3]*w.w;
    }
    int node = g_walksf[(size_t)seq*L_ + t + 1];
    float yt = y0[(size_t)node*OR_ + o];
    float term = g_posw * yt * softplusf(-acc) + (1.f - yt) * softplusf(acc);
    __shared__ float red[OR_];
    red[o] = term; __syncthreads();
    for (int st = OR_/2; st > 0; st >>= 1) { if (o < st) red[o] += red[o+st]; __syncthreads(); }
    if (o == 0) g_part2[b] = red[0];
}

__global__ void lred2_kernel(float* __restrict__ dst)
{
    __shared__ float red[256];
    int tid = threadIdx.x; float s = 0.f;
    for (int i = tid; i < NB_LOSS; i += 256) s += g_part2[i];
    red[tid] = s; __syncthreads();
    for (int st = 128; st > 0; st >>= 1) { if (tid < st) red[tid] += red[tid+st]; __syncthreads(); }
    if (tid == 0) *dst = red[0] / LOSS_CNT;
}

// ---------------- launch ----------------
extern "C" void kernel_launch(void* const* d_in, const int* in_sizes, int n_in,
                              void* d_out, int out_size)
{
    const float* h     = (const float*)d_in[0];
    const float* y0    = (const float*)d_in[1];
    const float* Wih_w = (const float*)d_in[2];
    const float* Whh_w = (const float*)d_in[3];
    const float* bih_w = (const float*)d_in[4];
    const float* bhh_w = (const float*)d_in[5];
    const float* Wih   = (const float*)d_in[6];
    const float* Whh   = (const float*)d_in[7];
    const float* bih   = (const float*)d_in[8];
    const float* bhh   = (const float*)d_in[9];
    const float* W_ss  = (const float*)d_in[10];
    const float* b_ss  = (const float*)d_in[11];
    const int*   walks = (const int*)d_in[12];
    const int*   idxs  = (const int*)d_in[13];
    float* out = (float*)d_out;

    const int SMEM_PT = 33792 + 34816;                 // 68608
    const int SMEM_G1 = 33792 + 69632 + G3_*4 + 256;   // 105216
    const int SMEM_G2 = 206848;
    cudaFuncSetAttribute(pT_kernel,   cudaFuncAttributeMaxDynamicSharedMemorySize, SMEM_PT);
    cudaFuncSetAttribute(gru1_kernel, cudaFuncAttributeMaxDynamicSharedMemorySize, SMEM_G1);
    cudaFuncSetAttribute(gru2_kernel, cudaFuncAttributeMaxDynamicSharedMemorySize, SMEM_G2);

    prep_kernel<<<(SEQ_ + 255)/256, 256>>>(walks);
    wg_kernel<<<1, G3_>>>(Wih_w, bih_w);
    pack_kernel<<<(G3_*F_ + 255)/256, 256>>>(Whh_w, Whh, Wih);
    packh_kernel<<<(NP_*F_ + 255)/256, 256>>>(h);
    pT_kernel<<<dim3(PTILES_, 3), NT_, SMEM_PT>>>(bih);
    gru1_kernel<<<TILES_, NT_, SMEM_G1>>>(bhh_w);
    gru2_kernel<<<T2_, NT2_, SMEM_G2>>>(bhh, out);
    lsum_kernel<<<NB_LOSS, OR_>>>(idxs, y0);
    lred1_kernel<<<1, 256>>>();
    lbce_kernel<<<NB_LOSS, OR_>>>(idxs, y0, W_ss, b_ss);
    lred2_kernel<<<1, 256>>>(out + (out_size - 1));
}

// round 12
// speedup vs baseline: 1.0581x; 1.0581x over previous
#include <cuda_runtime.h>
#include <cuda_bf16.h>
#include <math.h>
#include <stdint.h>

#define S_    4
#define N_    10000
#define NP_   10048
#define L_    8
#define F_    128
#define G3_   384
#define OR_   64
#define SUB_  100
#define SEQ_  (S_*N_)
#define MB_   64
#define NT_   256
#define NT1_  512
#define TILES_ (SEQ_/MB_)          // 625
#define PTILES_ (NP_/MB_)          // 157
#define NB_LOSS (S_*SUB_*(L_-1))
#define LOSS_CNT 179200.0f
#define APITCH 264
#define BPITCH 136
#define CHUNKE (128*BPITCH)

__device__ int      g_walksf[SEQ_*L_];
__device__ unsigned g_upk[SEQ_];
__device__ float    g_wg[8*G3_];
__device__ float    g_P[N_*G3_];
__device__ __nv_bfloat16 g_h2[(size_t)NP_*256];
__device__ __nv_bfloat16 g_yw2[(size_t)L_*SEQ_*256];
__device__ float    g_yseq[L_-1][SEQ_*F_];
__device__ float    g_part1[NB_LOSS];
__device__ float    g_part2[NB_LOSS];
__device__ float    g_posw;
__device__ __nv_bfloat16 g_W1h[G3_*F_], g_W1l[G3_*F_];
__device__ __nv_bfloat16 g_W2h[G3_*F_], g_W2l[G3_*F_];
__device__ __nv_bfloat16 g_WXh[G3_*F_], g_WXl[G3_*F_];
__device__ __nv_bfloat16 g_WAh[G3_*F_], g_WAl[G3_*F_];

__device__ __forceinline__ float sigf(float x) { return __fdividef(1.f, 1.f + __expf(-x)); }
__device__ __forceinline__ float tanh_s(float x) {
    float ax = fabsf(x); float e = __expf(-2.f*ax);
    return copysignf(__fdividef(1.f - e, 1.f + e), x);
}
__device__ __forceinline__ float softplusf(float x) {
    return fmaxf(x, 0.f) + log1pf(__expf(-fabsf(x)));
}
__device__ __forceinline__ float2 unpackbf(uint32_t u) {
    __nv_bfloat162 v = *(__nv_bfloat162*)&u;
    return make_float2(__bfloat162float(v.x), __bfloat162float(v.y));
}

__device__ __forceinline__ void mma16816(float c[4], uint32_t a0, uint32_t a1,
                                         uint32_t a2, uint32_t a3, uint32_t b0, uint32_t b1) {
    asm volatile("mma.sync.aligned.m16n8k16.row.col.f32.bf16.bf16.f32 "
                 "{%0,%1,%2,%3}, {%4,%5,%6,%7}, {%8,%9}, {%0,%1,%2,%3};\n"
                 : "+f"(c[0]), "+f"(c[1]), "+f"(c[2]), "+f"(c[3])
                 : "r"(a0), "r"(a1), "r"(a2), "r"(a3), "r"(b0), "r"(b1));
}
__device__ __forceinline__ void ldsm_x4(uint32_t& r0, uint32_t& r1, uint32_t& r2, uint32_t& r3,
                                        const void* p) {
    uint32_t a = (uint32_t)__cvta_generic_to_shared(p);
    asm volatile("ldmatrix.sync.aligned.m8n8.x4.shared.b16 {%0,%1,%2,%3}, [%4];"
                 : "=r"(r0), "=r"(r1), "=r"(r2), "=r"(r3) : "r"(a));
}

// single-chunk GEMMs (GRU2/pT): run2 = (Ahi+Alo)*W, run1 = Ahi*W
template<int WITH_LO>
__device__ __forceinline__ void run_seg(float (&acc)[2][4][4],
    const __nv_bfloat16* __restrict__ A, const __nv_bfloat16* __restrict__ W,
    int lane, int wc)
{
    const int rl = lane & 15;
    const int kp = (lane >> 4) << 3;
#pragma unroll
    for (int ks = 0; ks < 8; ks++) {
        const int k0 = ks*16 + kp;
        uint32_t ah[2][4], al[2][4];
#pragma unroll
        for (int mt = 0; mt < 2; mt++) {
            const __nv_bfloat16* Ar = A + (mt*16 + rl)*APITCH + k0;
            ldsm_x4(ah[mt][0], ah[mt][1], ah[mt][2], ah[mt][3], Ar);
            if (WITH_LO) ldsm_x4(al[mt][0], al[mt][1], al[mt][2], al[mt][3], Ar + 128);
        }
#pragma unroll
        for (int np = 0; np < 2; np++) {
            const __nv_bfloat16* Wr = W + (wc*32 + np*16 + rl)*BPITCH + k0;
            uint32_t bh[4];
            ldsm_x4(bh[0], bh[1], bh[2], bh[3], Wr);
#pragma unroll
            for (int mt = 0; mt < 2; mt++) {
                mma16816(acc[mt][np*2+0], ah[mt][0], ah[mt][1], ah[mt][2], ah[mt][3], bh[0], bh[2]);
                mma16816(acc[mt][np*2+1], ah[mt][0], ah[mt][1], ah[mt][2], ah[mt][3], bh[1], bh[3]);
                if (WITH_LO) {
                    mma16816(acc[mt][np*2+0], al[mt][0], al[mt][1], al[mt][2], al[mt][3], bh[0], bh[2]);
                    mma16816(acc[mt][np*2+1], al[mt][0], al[mt][1], al[mt][2], al[mt][3], bh[1], bh[3]);
                }
            }
        }
    }
}

// GRU1 resident-weight GEMM: 16-row A tile, swizzled pitch-128 B chunks (hi at Bq, lo at +32768B)
__device__ __forceinline__ void run_gemm1(float (&acc)[4][4],
    const __nv_bfloat16* __restrict__ A, const char* __restrict__ Bq,
    int lane, int wc)
{
    const int rl = lane & 15;
    const int kp = (lane >> 4) << 3;
#pragma unroll
    for (int ks = 0; ks < 8; ks++) {
        const int k0 = ks*16 + kp;
        uint32_t ah[4], al[4];
        const __nv_bfloat16* Ar = A + rl*APITCH + k0;
        ldsm_x4(ah[0], ah[1], ah[2], ah[3], Ar);
        ldsm_x4(al[0], al[1], al[2], al[3], Ar + 128);
#pragma unroll
        for (int np = 0; np < 2; np++) {
            uint32_t off = (uint32_t)(((wc*32 + np*16 + rl)*128 + k0)*2);
            uint32_t sw = off ^ ((off >> 3) & 0x70);
            uint32_t bh[4], bl[4];
            ldsm_x4(bh[0], bh[1], bh[2], bh[3], Bq + sw);
            ldsm_x4(bl[0], bl[1], bl[2], bl[3], Bq + 32768 + sw);
            mma16816(acc[np*2+0], ah[0], ah[1], ah[2], ah[3], bh[0], bh[2]);
            mma16816(acc[np*2+1], ah[0], ah[1], ah[2], ah[3], bh[1], bh[3]);
            mma16816(acc[np*2+0], al[0], al[1], al[2], al[3], bh[0], bh[2]);
            mma16816(acc[np*2+1], al[0], al[1], al[2], al[3], bh[1], bh[3]);
            mma16816(acc[np*2+0], ah[0], ah[1], ah[2], ah[3], bl[0], bl[2]);
            mma16816(acc[np*2+1], ah[0], ah[1], ah[2], ah[3], bl[1], bl[3]);
        }
    }
}

__device__ __forceinline__ void cpa16(uint32_t d, const void* s) {
    asm volatile("cp.async.cg.shared.global [%0], [%1], 16;\n" :: "r"(d), "l"(s));
}
// pT / GRU2 single-chunk staging (NT_=256)
__device__ __forceinline__ void stage1(uint32_t dstB, const __nv_bfloat16* __restrict__ src,
                                       int tid)
{
#pragma unroll
    for (int it = 0; it < 8; it++) {
        int i = tid + it*NT_;
        int row = i >> 4, seg = (i & 15) << 3;
        cpa16(dstB + (uint32_t)(row*BPITCH + seg)*2u, src + row*128 + seg);
    }
}
__device__ __forceinline__ void cp_wait_all() {
    asm volatile("cp.async.commit_group;\n");
    asm volatile("cp.async.wait_group 0;\n" ::: "memory");
}

// GRU1 gi loader (16-row warp tile)
__device__ __forceinline__ void load_gi1(float (&acc)[4][4], int jg, int t,
    const int* __restrict__ sh_i, const float* __restrict__ sh_bh, int addbias,
    int rbase, int g, int tg2, int wc)
{
    int u0 = (sh_i[rbase + g]     >> (4*t)) & 7;
    int u1 = (sh_i[rbase + g + 8] >> (4*t)) & 7;
#pragma unroll
    for (int nt = 0; nt < 4; nt++) {
        int cc = jg*F_ + wc*32 + nt*8 + tg2;
        float2 p0 = *(const float2*)&g_wg[u0*G3_ + cc];
        float2 p1 = *(const float2*)&g_wg[u1*G3_ + cc];
        acc[nt][0]=p0.x; acc[nt][1]=p0.y; acc[nt][2]=p1.x; acc[nt][3]=p1.y;
        if (addbias) {
            float2 bh = *(const float2*)&sh_bh[cc];
            acc[nt][0]+=bh.x; acc[nt][1]+=bh.y; acc[nt][2]+=bh.x; acc[nt][3]+=bh.y;
        }
    }
}

// GRU2 gi loader (P gather)
__device__ __forceinline__ void load_gi2(float (&acc)[2][4][4], int jg,
    const int* __restrict__ sh_i, const float* __restrict__ sh_bh, int addbias,
    int rbase, int g, int tg2, int wc)
{
#pragma unroll
    for (int mt = 0; mt < 2; mt++) {
        int i0 = sh_i[rbase + mt*16 + g], i1 = sh_i[rbase + mt*16 + g + 8];
#pragma unroll
        for (int nt = 0; nt < 4; nt++) {
            int cc = jg*F_ + wc*32 + nt*8 + tg2;
            float2 p0 = *(const float2*)&g_P[(size_t)i0*G3_ + cc];
            float2 p1 = *(const float2*)&g_P[(size_t)i1*G3_ + cc];
            acc[mt][nt][0]=p0.x; acc[mt][nt][1]=p0.y; acc[mt][nt][2]=p1.x; acc[mt][nt][3]=p1.y;
            if (addbias) {
                float2 bh = *(const float2*)&sh_bh[cc];
                acc[mt][nt][0]+=bh.x; acc[mt][nt][1]+=bh.y; acc[mt][nt][2]+=bh.x; acc[mt][nt][3]+=bh.y;
            }
        }
    }
}

// ---------------- preprocessing ----------------
__global__ void prep_kernel(const int* __restrict__ walks)
{
    int m = blockIdx.x * blockDim.x + threadIdx.x;
    if (m >= SEQ_) return;
    int w[L_];
#pragma unroll
    for (int p = 0; p < L_; p++) w[p] = walks[m*L_ + p];
    unsigned pk = 0;
#pragma unroll
    for (int t = 0; t < L_; t++) {
        int p = L_-1-t, wp = w[p], u = p;
#pragma unroll
        for (int q = L_-1; q >= 0; q--) if (w[q] == wp) u = q;
        g_walksf[m*L_ + t] = wp;
        pk |= ((unsigned)u) << (4*t);
    }
    g_upk[m] = pk;
}

__global__ void wg_kernel(const float* __restrict__ Wih_w, const float* __restrict__ bih_w)
{
    int j = threadIdx.x;
    float b = bih_w[j];
#pragma unroll
    for (int u = 0; u < 8; u++) g_wg[u*G3_ + j] = Wih_w[j*8 + u] + b;
}

__global__ void pack_kernel(const float* __restrict__ Whh_w, const float* __restrict__ Whh,
                            const float* __restrict__ Wih)
{
    int i = blockIdx.x * 256 + threadIdx.x;
    if (i >= G3_*F_) return;
    float a = Whh_w[i];
    __nv_bfloat16 h1 = __float2bfloat16(a);
    g_W1h[i] = h1; g_W1l[i] = __float2bfloat16(a - __bfloat162float(h1));
    float b = Whh[i];
    __nv_bfloat16 h2 = __float2bfloat16(b);
    g_W2h[i] = h2; g_W2l[i] = __float2bfloat16(b - __bfloat162float(h2));
    int n = i >> 7, k = i & 127;
    float c = Wih[n*256 + 128 + k];
    __nv_bfloat16 h3 = __float2bfloat16(c);
    g_WXh[i] = h3; g_WXl[i] = __float2bfloat16(c - __bfloat162float(h3));
    float d = Wih[n*256 + k];
    __nv_bfloat16 h4 = __float2bfloat16(d);
    g_WAh[i] = h4; g_WAl[i] = __float2bfloat16(d - __bfloat162float(h4));
}

__global__ void packh_kernel(const float* __restrict__ h)
{
    int i = blockIdx.x * 256 + threadIdx.x;
    if (i >= NP_*F_) return;
    int n = i >> 7, k = i & 127;
    float v = (n < N_) ? h[(size_t)n*F_ + k] : 0.f;
    __nv_bfloat16 hi = __float2bfloat16(v);
    g_h2[(size_t)n*256 + k]       = hi;
    g_h2[(size_t)n*256 + 128 + k] = __float2bfloat16(v - __bfloat162float(hi));
}

// ---------------- P = h @ WihA^T + bih (tensor cores) ----------------
__global__ void __launch_bounds__(NT_) pT_kernel(const float* __restrict__ bih)
{
    extern __shared__ char smc[];
    __nv_bfloat16* sh_x2 = (__nv_bfloat16*)smc;            // 33792
    __nv_bfloat16* sh_W  = (__nv_bfloat16*)(smc + 33792);  // 34816

    const int tid = threadIdx.x, wid = tid >> 5, lane = tid & 31;
    const int wr = wid & 1, wc = wid >> 1;
    const int g = lane >> 2, tg2 = (lane & 3)*2;
    const int rbase = wr*32;
    const int m0 = blockIdx.x*MB_, jg = blockIdx.y;
    const uint32_t sWu = (uint32_t)__cvta_generic_to_shared(sh_W);

#pragma unroll
    for (int it = 0; it < 8; it++) {
        int i = tid + it*NT_;
        int row = i >> 5, seg = (i & 31) << 3;
        *(uint4*)(sh_x2 + row*APITCH + seg) =
            *(const uint4*)(g_h2 + ((size_t)(m0 + row))*256 + seg);
    }
    stage1(sWu, g_WAh + (size_t)jg*16384, tid);
    cp_wait_all();
    __syncthreads();

    float acc[2][4][4];
#pragma unroll
    for (int mt = 0; mt < 2; mt++)
#pragma unroll
        for (int nt = 0; nt < 4; nt++) {
            int cc = jg*F_ + wc*32 + nt*8 + tg2;
            float2 b = *(const float2*)&bih[cc];
            acc[mt][nt][0]=b.x; acc[mt][nt][1]=b.y; acc[mt][nt][2]=b.x; acc[mt][nt][3]=b.y;
        }
    run_seg<1>(acc, sh_x2 + rbase*APITCH, sh_W, lane, wc);
    __syncthreads();
    stage1(sWu, g_WAl + (size_t)jg*16384, tid);
    cp_wait_all();
    __syncthreads();
    run_seg<0>(acc, sh_x2 + rbase*APITCH, sh_W, lane, wc);

#pragma unroll
    for (int mt = 0; mt < 2; mt++)
#pragma unroll
        for (int nt = 0; nt < 4; nt++) {
            int cc = jg*F_ + wc*32 + nt*8 + tg2;
#pragma unroll
            for (int p2 = 0; p2 < 2; p2++) {
                int n = m0 + rbase + mt*16 + g + p2*8;
                if (n < N_)
                    *(float2*)&g_P[(size_t)n*G3_ + cc] =
                        make_float2(acc[mt][nt][p2*2], acc[mt][nt][p2*2+1]);
            }
        }
}

// ---------------- GRU1: weights resident in smem, 512 threads ----------------
__global__ void __launch_bounds__(NT1_, 1) gru1_kernel(const float* __restrict__ bhh)
{
    extern __shared__ char smc[];
    char* sh_Wq = smc;                                  // 6*32768 = 196608 (swizzled chunks)
    __nv_bfloat16* sh_h2 = (__nv_bfloat16*)(smc + 196608);   // 33792
    float* sh_bh = (float*)(smc + 196608 + 33792);           // 1536
    int*   sh_i  = (int*)(smc + 196608 + 33792 + 1536);      // 256

    const int tid = threadIdx.x, wid = tid >> 5, lane = tid & 31;
    const int wr = wid & 3, wc = wid >> 2;     // 4 row-warps (16 rows) x 4 col-warps (32 cols)
    const int g = lane >> 2, tg2 = (lane & 3)*2;
    const int rbase = wr*16;
    const int m0 = blockIdx.x*MB_;
    const uint32_t sWu = (uint32_t)__cvta_generic_to_shared(sh_Wq);

    // stage all 6 weight chunks once (swizzled, pitch-128)
    for (int i = tid; i < 6*2048; i += NT1_) {
        int q = i >> 11;                       // chunk: gate*2 + (hi=0/lo=1)
        uint32_t off = (uint32_t)(i & 2047) << 4;
        uint32_t sw = off ^ ((off >> 3) & 0x70);
        const __nv_bfloat16* src = ((q & 1) ? g_W1l : g_W1h) + (q >> 1)*16384 + (off >> 1);
        cpa16(sWu + (uint32_t)q*32768u + sw, src);
    }
    for (int i = tid; i < G3_; i += NT1_) sh_bh[i] = bhh[i];
    for (int i = tid; i < MB_*APITCH/2; i += NT1_) ((uint32_t*)sh_h2)[i] = 0u;
    if (tid < MB_) sh_i[tid] = (int)g_upk[m0 + tid];
    cp_wait_all();
    __syncthreads();

#pragma unroll 1
    for (int t = 0; t < L_; t++) {
        const bool doH = (t > 0);
        float rr[4][4], zz[4][4], ai[4][4], ah2[4][4];
        const __nv_bfloat16* Aw = sh_h2 + rbase*APITCH;

        load_gi1(rr, 0, t, sh_i, sh_bh, 1, rbase, g, tg2, wc);
        if (doH) run_gemm1(rr, Aw, sh_Wq, lane, wc);
#pragma unroll
        for (int nt=0; nt<4; nt++)
#pragma unroll
            for (int q=0; q<4; q++) rr[nt][q] = sigf(rr[nt][q]);

        load_gi1(zz, 1, t, sh_i, sh_bh, 1, rbase, g, tg2, wc);
        if (doH) run_gemm1(zz, Aw, sh_Wq + 2*32768, lane, wc);
#pragma unroll
        for (int nt=0; nt<4; nt++)
#pragma unroll
            for (int q=0; q<4; q++) zz[nt][q] = sigf(zz[nt][q]);

        load_gi1(ai, 2, t, sh_i, nullptr, 0, rbase, g, tg2, wc);
#pragma unroll
        for (int nt=0; nt<4; nt++) {
            int cc = 2*F_ + wc*32 + nt*8 + tg2;
            float2 bh = *(const float2*)&sh_bh[cc];
            ah2[nt][0]=bh.x; ah2[nt][1]=bh.y; ah2[nt][2]=bh.x; ah2[nt][3]=bh.y;
        }
        if (doH) run_gemm1(ah2, Aw, sh_Wq + 4*32768, lane, wc);

        float nn[4][4];
#pragma unroll
        for (int nt=0; nt<4; nt++)
#pragma unroll
            for (int q=0; q<4; q++)
                nn[nt][q] = tanh_s(ai[nt][q] + rr[nt][q]*ah2[nt][q]);

        __syncthreads();   // all h reads complete
#pragma unroll
        for (int nt=0; nt<4; nt++) {
            int cc = wc*32 + nt*8 + tg2;
#pragma unroll
            for (int p2=0; p2<2; p2++) {
                int r = rbase + g + p2*8;
                float n0 = nn[nt][p2*2], n1 = nn[nt][p2*2+1];
                float z0 = zz[nt][p2*2], z1 = zz[nt][p2*2+1];
                float2 hh = unpackbf(*(uint32_t*)&sh_h2[r*APITCH + cc]);
                float2 hl = unpackbf(*(uint32_t*)&sh_h2[r*APITCH + 128 + cc]);
                float h0 = (1.f - z0)*n0 + z0*(hh.x + hl.x);
                float h1 = (1.f - z1)*n1 + z1*(hh.y + hl.y);
                __nv_bfloat16 s0 = __float2bfloat16(h0), s1 = __float2bfloat16(h1);
                __nv_bfloat162 hv; hv.x = s0; hv.y = s1;
                uint32_t hiv = *(uint32_t*)&hv;
                __nv_bfloat162 lv = __floats2bfloat162_rn(h0 - __bfloat162float(s0),
                                                          h1 - __bfloat162float(s1));
                uint32_t lov = *(uint32_t*)&lv;
                *(uint32_t*)&sh_h2[r*APITCH + cc] = hiv;
                *(uint32_t*)&sh_h2[r*APITCH + 128 + cc] = lov;
                size_t base = ((size_t)t*SEQ_ + m0 + r)*256 + cc;
                *(uint32_t*)&g_yw2[base]       = hiv;
                *(uint32_t*)&g_yw2[base + 128] = lov;
            }
        }
        __syncthreads();   // h update visible before next step
    }
}

// ---------------- GRU2 (round-10: single-chunk staging, 2 blocks/SM) ----------------
__device__ __forceinline__ void gate_gemm(float (&ax)[2][4][4], float (&ah2)[2][4][4], int jg,
    const __nv_bfloat16* sh_x2, const __nv_bfloat16* sh_h2, uint32_t sWu,
    const __nv_bfloat16* sh_W, int tid, int lane, int wc, int rbase)
{
    stage1(sWu, g_WXh + (size_t)jg*16384, tid);
    cp_wait_all(); __syncthreads();
    run_seg<1>(ax, sh_x2 + rbase*APITCH, sh_W, lane, wc);
    __syncthreads();
    stage1(sWu, g_WXl + (size_t)jg*16384, tid);
    cp_wait_all(); __syncthreads();
    run_seg<0>(ax, sh_x2 + rbase*APITCH, sh_W, lane, wc);
    __syncthreads();
    stage1(sWu, g_W2h + (size_t)jg*16384, tid);
    cp_wait_all(); __syncthreads();
    run_seg<1>(ah2, sh_h2 + rbase*APITCH, sh_W, lane, wc);
    __syncthreads();
    stage1(sWu, g_W2l + (size_t)jg*16384, tid);
    cp_wait_all(); __syncthreads();
    run_seg<0>(ah2, sh_h2 + rbase*APITCH, sh_W, lane, wc);
}

__global__ void __launch_bounds__(NT_, 2) gru2_kernel(const float* __restrict__ bhh,
                                                      float* __restrict__ hT_out)
{
    extern __shared__ char smc[];
    __nv_bfloat16* sh_h2 = (__nv_bfloat16*)smc;                  // 33792
    __nv_bfloat16* sh_x2 = (__nv_bfloat16*)(smc + 33792);        // 33792
    __nv_bfloat16* sh_W  = (__nv_bfloat16*)(smc + 67584);        // 34816
    float* sh_bh = (float*)(smc + 102400);                       // 1536
    int*   sh_i  = (int*)(smc + 103936);                         // 256

    const int tid = threadIdx.x, wid = tid >> 5, lane = tid & 31;
    const int wr = wid & 1, wc = wid >> 1;
    const int g = lane >> 2, tg2 = (lane & 3)*2;
    const int rbase = wr*32;
    const int m0 = blockIdx.x*MB_;
    const uint32_t sWu = (uint32_t)__cvta_generic_to_shared(sh_W);

    for (int i = tid; i < G3_; i += NT_) sh_bh[i] = bhh[i];
#pragma unroll
    for (int it = 0; it < 8; it++) {
        int i = tid + it*NT_;
        int row = i >> 5, seg = (i & 31) << 3;
        *(uint4*)(sh_h2 + row*APITCH + seg) =
            *(const uint4*)(g_yw2 + ((size_t)(L_-1)*SEQ_ + m0 + row)*256 + seg);
    }

#pragma unroll 1
    for (int t = 0; t < L_; t++) {
        __syncthreads();
#pragma unroll
        for (int it = 0; it < 8; it++) {
            int i = tid + it*NT_;
            int row = i >> 5, seg = (i & 31) << 3;
            *(uint4*)(sh_x2 + row*APITCH + seg) =
                *(const uint4*)(g_yw2 + ((size_t)t*SEQ_ + m0 + row)*256 + seg);
        }
        if (tid < MB_) sh_i[tid] = g_walksf[(size_t)(m0 + tid)*L_ + t];
        __syncthreads();

        float nn[2][4][4];
        {
            float rr[2][4][4];
            load_gi2(rr, 0, sh_i, sh_bh, 1, rbase, g, tg2, wc);
            gate_gemm(rr, rr, 0, sh_x2, sh_h2, sWu, sh_W, tid, lane, wc, rbase);
#pragma unroll
            for (int mt=0; mt<2; mt++)
#pragma unroll
                for (int nt=0; nt<4; nt++)
#pragma unroll
                    for (int q=0; q<4; q++) rr[mt][nt][q] = sigf(rr[mt][nt][q]);

            __syncthreads();
            float acci[2][4][4], acch[2][4][4];
            load_gi2(acci, 2, sh_i, nullptr, 0, rbase, g, tg2, wc);
#pragma unroll
            for (int mt=0; mt<2; mt++)
#pragma unroll
                for (int nt=0; nt<4; nt++) {
                    int cc = 2*F_ + wc*32 + nt*8 + tg2;
                    float2 bh = *(const float2*)&sh_bh[cc];
                    acch[mt][nt][0]=bh.x; acch[mt][nt][1]=bh.y;
                    acch[mt][nt][2]=bh.x; acch[mt][nt][3]=bh.y;
                }
            gate_gemm(acci, acch, 2, sh_x2, sh_h2, sWu, sh_W, tid, lane, wc, rbase);
#pragma unroll
            for (int mt=0; mt<2; mt++)
#pragma unroll
                for (int nt=0; nt<4; nt++)
#pragma unroll
                    for (int q=0; q<4; q++)
                        nn[mt][nt][q] = tanh_s(acci[mt][nt][q] + rr[mt][nt][q]*acch[mt][nt][q]);
        }

        float zz[2][4][4];
        __syncthreads();
        load_gi2(zz, 1, sh_i, sh_bh, 1, rbase, g, tg2, wc);
        gate_gemm(zz, zz, 1, sh_x2, sh_h2, sWu, sh_W, tid, lane, wc, rbase);
#pragma unroll
        for (int mt=0; mt<2; mt++)
#pragma unroll
            for (int nt=0; nt<4; nt++)
#pragma unroll
                for (int q=0; q<4; q++) zz[mt][nt][q] = sigf(zz[mt][nt][q]);

        __syncthreads();
#pragma unroll
        for (int mt=0; mt<2; mt++)
#pragma unroll
            for (int nt=0; nt<4; nt++) {
                int cc = wc*32 + nt*8 + tg2;
#pragma unroll
                for (int p2=0; p2<2; p2++) {
                    int r = rbase + mt*16 + g + p2*8;
                    float n0 = nn[mt][nt][p2*2], n1 = nn[mt][nt][p2*2+1];
                    float z0 = zz[mt][nt][p2*2], z1 = zz[mt][nt][p2*2+1];
                    float2 hh = unpackbf(*(uint32_t*)&sh_h2[r*APITCH + cc]);
                    float2 hl = unpackbf(*(uint32_t*)&sh_h2[r*APITCH + 128 + cc]);
                    float h0 = (1.f - z0)*n0 + z0*(hh.x + hl.x);
                    float h1 = (1.f - z1)*n1 + z1*(hh.y + hl.y);
                    __nv_bfloat16 s0 = __float2bfloat16(h0), s1 = __float2bfloat16(h1);
                    __nv_bfloat162 hv; hv.x = s0; hv.y = s1;
                    uint32_t hiv = *(uint32_t*)&hv;
                    __nv_bfloat162 lv = __floats2bfloat162_rn(h0 - __bfloat162float(s0),
                                                              h1 - __bfloat162float(s1));
                    uint32_t lov = *(uint32_t*)&lv;
                    *(uint32_t*)&sh_h2[r*APITCH + cc] = hiv;
                    *(uint32_t*)&sh_h2[r*APITCH + 128 + cc] = lov;
                    float* dst = (t < L_-1) ? (g_yseq[t] + ((size_t)(m0+r))*F_ + cc)
                                            : (hT_out   + ((size_t)(m0+r))*F_ + cc);
                    *(float2*)dst = make_float2(h0, h1);
                }
            }
    }
}

// ---------------- loss ----------------
__global__ void lsum_kernel(const int* __restrict__ idxs, const float* __restrict__ y0)
{
    int b = blockIdx.x;
    int t = b % (L_-1), j = (b/(L_-1)) % SUB_, s = b/((L_-1)*SUB_);
    int seq = s*N_ + idxs[j];
    int node = g_walksf[(size_t)seq*L_ + t + 1];
    int o = threadIdx.x;
    __shared__ float red[OR_];
    red[o] = y0[(size_t)node*OR_ + o]; __syncthreads();
    for (int st = OR_/2; st > 0; st >>= 1) { if (o < st) red[o] += red[o+st]; __syncthreads(); }
    if (o == 0) g_part1[b] = red[0];
}

__global__ void lred1_kernel()
{
    __shared__ float red[256];
    int tid = threadIdx.x; float s = 0.f;
    for (int i = tid; i < NB_LOSS; i += 256) s += g_part1[i];
    red[tid] = s; __syncthreads();
    for (int st = 128; st > 0; st >>= 1) { if (tid < st) red[tid] += red[tid+st]; __syncthreads(); }
    if (tid == 0) g_posw = LOSS_CNT / red[0];
}

__global__ void lbce_kernel(const int* __restrict__ idxs, const float* __restrict__ y0,
                            const float* __restrict__ Wss, const float* __restrict__ bss)
{
    int b = blockIdx.x;
    int t = b % (L_-1), j = (b/(L_-1)) % SUB_, s = b/((L_-1)*SUB_);
    int seq = s*N_ + idxs[j];
    __shared__ float yrow[F_];
    int o = threadIdx.x;
    yrow[o]      = g_yseq[t][(size_t)seq*F_ + o];
    yrow[o + 64] = g_yseq[t][(size_t)seq*F_ + o + 64];
    __syncthreads();
    float acc = bss[o];
    const float4* wrp = (const float4*)(Wss + (size_t)o*F_);
#pragma unroll 8
    for (int k = 0; k < F_/4; k++) {
        float4 w = wrp[k];
        acc += yrow[k*4]*w.x + yrow[k*4+1]*w.y + yrow[k*4+2]*w.z + yrow[k*4+3]*w.w;
    }
    int node = g_walksf[(size_t)seq*L_ + t + 1];
    float yt = y0[(size_t)node*OR_ + o];
    float term = g_posw * yt * softplusf(-acc) + (1.f - yt) * softplusf(acc);
    __shared__ float red[OR_];
    red[o] = term; __syncthreads();
    for (int st = OR_/2; st > 0; st >>= 1) { if (o < st) red[o] += red[o+st]; __syncthreads(); }
    if (o == 0) g_part2[b] = red[0];
}

__global__ void lred2_kernel(float* __restrict__ dst)
{
    __shared__ float red[256];
    int tid = threadIdx.x; float s = 0.f;
    for (int i = tid; i < NB_LOSS; i += 256) s += g_part2[i];
    red[tid] = s; __syncthreads();
    for (int st = 128; st > 0; st >>= 1) { if (tid < st) red[tid] += red[tid+st]; __syncthreads(); }
    if (tid == 0) *dst = red[0] / LOSS_CNT;
}

// ---------------- launch ----------------
extern "C" void kernel_launch(void* const* d_in, const int* in_sizes, int n_in,
                              void* d_out, int out_size)
{
    const float* h     = (const float*)d_in[0];
    const float* y0    = (const float*)d_in[1];
    const float* Wih_w = (const float*)d_in[2];
    const float* Whh_w = (const float*)d_in[3];
    const float* bih_w = (const float*)d_in[4];
    const float* bhh_w = (const float*)d_in[5];
    const float* Wih   = (const float*)d_in[6];
    const float* Whh   = (const float*)d_in[7];
    const float* bih   = (const float*)d_in[8];
    const float* bhh   = (const float*)d_in[9];
    const float* W_ss  = (const float*)d_in[10];
    const float* b_ss  = (const float*)d_in[11];
    const int*   walks = (const int*)d_in[12];
    const int*   idxs  = (const int*)d_in[13];
    float* out = (float*)d_out;

    const int SMEM_PT = 33792 + 34816;                     // 68608
    const int SMEM_G1 = 196608 + 33792 + 1536 + 256;       // 232192
    const int SMEM_G2 = 104192;
    cudaFuncSetAttribute(pT_kernel,   cudaFuncAttributeMaxDynamicSharedMemorySize, SMEM_PT);
    cudaFuncSetAttribute(gru1_kernel, cudaFuncAttributeMaxDynamicSharedMemorySize, SMEM_G1);
    cudaFuncSetAttribute(gru2_kernel, cudaFuncAttributeMaxDynamicSharedMemorySize, SMEM_G2);

    prep_kernel<<<(SEQ_ + 255)/256, 256>>>(walks);
    wg_kernel<<<1, G3_>>>(Wih_w, bih_w);
    pack_kernel<<<(G3_*F_ + 255)/256, 256>>>(Whh_w, Whh, Wih);
    packh_kernel<<<(NP_*F_ + 255)/256, 256>>>(h);
    pT_kernel<<<dim3(PTILES_, 3), NT_, SMEM_PT>>>(bih);
    gru1_kernel<<<TILES_, NT1_, SMEM_G1>>>(bhh_w);
    gru2_kernel<<<TILES_, NT_, SMEM_G2>>>(bhh, out);
    lsum_kernel<<<NB_LOSS, OR_>>>(idxs, y0);
    lred1_kernel<<<1, 256>>>();
    lbce_kernel<<<NB_LOSS, OR_>>>(idxs, y0, W_ss, b_ss);
    lred2_kernel<<<1, 256>>>(out + (out_size - 1));
}

// round 13
// speedup vs baseline: 1.9999x; 1.8901x over previous
#include <cuda_runtime.h>
#include <cuda_fp16.h>
#include <math.h>
#include <stdint.h>

#define S_    4
#define N_    10000
#define NP_   10048
#define L_    8
#define F_    128
#define G3_   384
#define OR_   64
#define SUB_  100
#define SEQ_  (S_*N_)
#define MB_   64
#define NT_   256
#define TILES_ (SEQ_/MB_)          // 625
#define PTILES_ (NP_/MB_)          // 157
#define NB_LOSS (S_*SUB_*(L_-1))
#define LOSS_CNT 179200.0f
#define HP_   136                  // fp16 tile pitch (bank-safe)
#define FP_   132                  // fp32 h-state pitch

__device__ int      g_walksf[SEQ_*L_];
__device__ unsigned g_upk[SEQ_];
__device__ float    g_wg[8*G3_];
__device__ float    g_P[N_*G3_];
__device__ __half   g_hH[(size_t)NP_*F_];             // h fp16
__device__ __half   g_ywH[(size_t)L_*SEQ_*F_];        // GRU1 out fp16
__device__ float    g_yseq[L_-1][SEQ_*F_];
__device__ float    g_part1[NB_LOSS];
__device__ float    g_part2[NB_LOSS];
__device__ float    g_posw;
__device__ __half   g_W1[G3_*F_];                     // Whh_w fp16
__device__ __half   g_W2[G3_*F_];                     // Whh fp16
__device__ __half   g_WX[G3_*F_];                     // Wih[:,128:256] fp16
__device__ __half   g_WA[G3_*F_];                     // Wih[:,0:128] fp16

__device__ __forceinline__ float sigf(float x) { return __fdividef(1.f, 1.f + __expf(-x)); }
__device__ __forceinline__ float tanh_s(float x) {
    float ax = fabsf(x); float e = __expf(-2.f*ax);
    return copysignf(__fdividef(1.f - e, 1.f + e), x);
}
__device__ __forceinline__ float softplusf(float x) {
    return fmaxf(x, 0.f) + log1pf(__expf(-fabsf(x)));
}

__device__ __forceinline__ void mma_f16(float c[4], uint32_t a0, uint32_t a1,
                                        uint32_t a2, uint32_t a3, uint32_t b0, uint32_t b1) {
    asm volatile("mma.sync.aligned.m16n8k16.row.col.f32.f16.f16.f32 "
                 "{%0,%1,%2,%3}, {%4,%5,%6,%7}, {%8,%9}, {%0,%1,%2,%3};\n"
                 : "+f"(c[0]), "+f"(c[1]), "+f"(c[2]), "+f"(c[3])
                 : "r"(a0), "r"(a1), "r"(a2), "r"(a3), "r"(b0), "r"(b1));
}
__device__ __forceinline__ void ldsm_x4(uint32_t& r0, uint32_t& r1, uint32_t& r2, uint32_t& r3,
                                        const void* p) {
    uint32_t a = (uint32_t)__cvta_generic_to_shared(p);
    asm volatile("ldmatrix.sync.aligned.m8n8.x4.shared.b16 {%0,%1,%2,%3}, [%4];"
                 : "=r"(r0), "=r"(r1), "=r"(r2), "=r"(r3) : "r"(a));
}

// fp16 single-pass GEMM: acc[2][4][4] += A(32x128, pitch HP_) @ W^T (128x128, pitch HP_)
__device__ __forceinline__ void run_f16(float (&acc)[2][4][4],
    const __half* __restrict__ A, const __half* __restrict__ W, int lane, int wc)
{
    const int rl = lane & 15;
    const int kp = (lane >> 4) << 3;
#pragma unroll
    for (int ks = 0; ks < 8; ks++) {
        const int k0 = ks*16 + kp;
        uint32_t a[2][4];
#pragma unroll
        for (int mt = 0; mt < 2; mt++)
            ldsm_x4(a[mt][0], a[mt][1], a[mt][2], a[mt][3], A + (mt*16 + rl)*HP_ + k0);
#pragma unroll
        for (int np = 0; np < 2; np++) {
            uint32_t b[4];
            ldsm_x4(b[0], b[1], b[2], b[3], W + (wc*32 + np*16 + rl)*HP_ + k0);
#pragma unroll
            for (int mt = 0; mt < 2; mt++) {
                mma_f16(acc[mt][np*2+0], a[mt][0], a[mt][1], a[mt][2], a[mt][3], b[0], b[2]);
                mma_f16(acc[mt][np*2+1], a[mt][0], a[mt][1], a[mt][2], a[mt][3], b[1], b[3]);
            }
        }
    }
}

__device__ __forceinline__ void cpa16(uint32_t d, const void* s) {
    asm volatile("cp.async.cg.shared.global [%0], [%1], 16;\n" :: "r"(d), "l"(s));
}
// stage one 128x128 fp16 chunk (NT_=256): 2048 x 16B
__device__ __forceinline__ void stage1(uint32_t dstB, const __half* __restrict__ src, int tid)
{
#pragma unroll
    for (int it = 0; it < 8; it++) {
        int i = tid + it*NT_;
        int row = i >> 4, seg = (i & 15) << 3;
        cpa16(dstB + (uint32_t)(row*HP_ + seg)*2u, src + row*128 + seg);
    }
}
__device__ __forceinline__ void cp_wait_all() {
    asm volatile("cp.async.commit_group;\n");
    asm volatile("cp.async.wait_group 0;\n" ::: "memory");
}

// gi loaders (fp32 sources)
__device__ __forceinline__ void load_gi1(float (&acc)[2][4][4], int jg, int t,
    const int* __restrict__ sh_i, const float* __restrict__ sh_bh, int addbias,
    int rbase, int g, int tg2, int wc)
{
#pragma unroll
    for (int mt = 0; mt < 2; mt++) {
        int u0 = (sh_i[rbase + mt*16 + g]     >> (4*t)) & 7;
        int u1 = (sh_i[rbase + mt*16 + g + 8] >> (4*t)) & 7;
#pragma unroll
        for (int nt = 0; nt < 4; nt++) {
            int cc = jg*F_ + wc*32 + nt*8 + tg2;
            float2 p0 = *(const float2*)&g_wg[u0*G3_ + cc];
            float2 p1 = *(const float2*)&g_wg[u1*G3_ + cc];
            acc[mt][nt][0]=p0.x; acc[mt][nt][1]=p0.y; acc[mt][nt][2]=p1.x; acc[mt][nt][3]=p1.y;
            if (addbias) {
                float2 bh = *(const float2*)&sh_bh[cc];
                acc[mt][nt][0]+=bh.x; acc[mt][nt][1]+=bh.y; acc[mt][nt][2]+=bh.x; acc[mt][nt][3]+=bh.y;
            }
        }
    }
}
__device__ __forceinline__ void load_gi2(float (&acc)[2][4][4], int jg,
    const int* __restrict__ sh_i, const float* __restrict__ sh_bh, int addbias,
    int rbase, int g, int tg2, int wc)
{
#pragma unroll
    for (int mt = 0; mt < 2; mt++) {
        int i0 = sh_i[rbase + mt*16 + g], i1 = sh_i[rbase + mt*16 + g + 8];
#pragma unroll
        for (int nt = 0; nt < 4; nt++) {
            int cc = jg*F_ + wc*32 + nt*8 + tg2;
            float2 p0 = *(const float2*)&g_P[(size_t)i0*G3_ + cc];
            float2 p1 = *(const float2*)&g_P[(size_t)i1*G3_ + cc];
            acc[mt][nt][0]=p0.x; acc[mt][nt][1]=p0.y; acc[mt][nt][2]=p1.x; acc[mt][nt][3]=p1.y;
            if (addbias) {
                float2 bh = *(const float2*)&sh_bh[cc];
                acc[mt][nt][0]+=bh.x; acc[mt][nt][1]+=bh.y; acc[mt][nt][2]+=bh.x; acc[mt][nt][3]+=bh.y;
            }
        }
    }
}

// ---------------- preprocessing ----------------
__global__ void prep_kernel(const int* __restrict__ walks)
{
    int m = blockIdx.x * blockDim.x + threadIdx.x;
    if (m >= SEQ_) return;
    int w[L_];
#pragma unroll
    for (int p = 0; p < L_; p++) w[p] = walks[m*L_ + p];
    unsigned pk = 0;
#pragma unroll
    for (int t = 0; t < L_; t++) {
        int p = L_-1-t, wp = w[p], u = p;
#pragma unroll
        for (int q = L_-1; q >= 0; q--) if (w[q] == wp) u = q;
        g_walksf[m*L_ + t] = wp;
        pk |= ((unsigned)u) << (4*t);
    }
    g_upk[m] = pk;
}

__global__ void wg_kernel(const float* __restrict__ Wih_w, const float* __restrict__ bih_w)
{
    int j = threadIdx.x;
    float b = bih_w[j];
#pragma unroll
    for (int u = 0; u < 8; u++) g_wg[u*G3_ + j] = Wih_w[j*8 + u] + b;
}

__global__ void pack_kernel(const float* __restrict__ Whh_w, const float* __restrict__ Whh,
                            const float* __restrict__ Wih)
{
    int i = blockIdx.x * 256 + threadIdx.x;
    if (i >= G3_*F_) return;
    g_W1[i] = __float2half(Whh_w[i]);
    g_W2[i] = __float2half(Whh[i]);
    int n = i >> 7, k = i & 127;
    g_WX[i] = __float2half(Wih[n*256 + 128 + k]);
    g_WA[i] = __float2half(Wih[n*256 + k]);
}

__global__ void packh_kernel(const float* __restrict__ h)
{
    int i = blockIdx.x * 256 + threadIdx.x;
    if (i >= NP_*F_) return;
    int n = i >> 7, k = i & 127;
    float v = (n < N_) ? h[(size_t)n*F_ + k] : 0.f;
    g_hH[(size_t)n*F_ + k] = __float2half(v);
}

// ---------------- P = h @ WihA^T + bih (fp16 tensor cores) ----------------
__global__ void __launch_bounds__(NT_) pT_kernel(const float* __restrict__ bih)
{
    extern __shared__ char smc[];
    __half* sh_x = (__half*)smc;                  // 64*HP_*2 = 17408
    __half* sh_W = (__half*)(smc + 17408);        // 128*HP_*2 = 34816

    const int tid = threadIdx.x, wid = tid >> 5, lane = tid & 31;
    const int wr = wid & 1, wc = wid >> 1;
    const int g = lane >> 2, tg2 = (lane & 3)*2;
    const int rbase = wr*32;
    const int m0 = blockIdx.x*MB_, jg = blockIdx.y;
    const uint32_t sWu = (uint32_t)__cvta_generic_to_shared(sh_W);

#pragma unroll
    for (int it = 0; it < 4; it++) {
        int i = tid + it*NT_;
        int row = i >> 4, seg = (i & 15) << 3;
        *(uint4*)(sh_x + row*HP_ + seg) = *(const uint4*)(g_hH + (size_t)(m0 + row)*F_ + seg);
    }
    stage1(sWu, g_WA + (size_t)jg*16384, tid);
    cp_wait_all();
    __syncthreads();

    float acc[2][4][4];
#pragma unroll
    for (int mt = 0; mt < 2; mt++)
#pragma unroll
        for (int nt = 0; nt < 4; nt++) {
            int cc = jg*F_ + wc*32 + nt*8 + tg2;
            float2 b = *(const float2*)&bih[cc];
            acc[mt][nt][0]=b.x; acc[mt][nt][1]=b.y; acc[mt][nt][2]=b.x; acc[mt][nt][3]=b.y;
        }
    run_f16(acc, sh_x + rbase*HP_, sh_W, lane, wc);

#pragma unroll
    for (int mt = 0; mt < 2; mt++)
#pragma unroll
        for (int nt = 0; nt < 4; nt++) {
            int cc = jg*F_ + wc*32 + nt*8 + tg2;
#pragma unroll
            for (int p2 = 0; p2 < 2; p2++) {
                int n = m0 + rbase + mt*16 + g + p2*8;
                if (n < N_)
                    *(float2*)&g_P[(size_t)n*G3_ + cc] =
                        make_float2(acc[mt][nt][p2*2], acc[mt][nt][p2*2+1]);
            }
        }
}

// ---------------- GRU1: fp16 single-pass, fp32 h state, 2 blocks/SM ----------------
__global__ void __launch_bounds__(NT_, 2) gru1_kernel(const float* __restrict__ bhh)
{
    extern __shared__ char smc[];
    float*  sh_hf = (float*)smc;                         // 64*FP_*4 = 33792
    __half* sh_ha = (__half*)(smc + 33792);              // 64*HP_*2 = 17408
    __half* sh_W  = (__half*)(smc + 33792 + 17408);      // 34816
    float*  sh_bh = (float*)(smc + 33792 + 17408 + 34816);  // 1536
    int*    sh_i  = (int*)(smc + 33792 + 17408 + 34816 + 1536);

    const int tid = threadIdx.x, wid = tid >> 5, lane = tid & 31;
    const int wr = wid & 1, wc = wid >> 1;
    const int g = lane >> 2, tg2 = (lane & 3)*2;
    const int rbase = wr*32;
    const int m0 = blockIdx.x*MB_;
    const uint32_t sWu = (uint32_t)__cvta_generic_to_shared(sh_W);

    for (int i = tid; i < G3_; i += NT_) sh_bh[i] = bhh[i];
    for (int i = tid; i < MB_*FP_; i += NT_) sh_hf[i] = 0.f;
    for (int i = tid; i < MB_*HP_/2; i += NT_) ((uint32_t*)sh_ha)[i] = 0u;
    if (tid < MB_) sh_i[tid] = (int)g_upk[m0 + tid];

#pragma unroll 1
    for (int t = 0; t < L_; t++) {
        const bool doH = (t > 0);
        float nn[2][4][4];
        {
            // gate r
            float rr[2][4][4];
            __syncthreads();
            if (doH) { stage1(sWu, g_W1, tid); cp_wait_all(); }
            __syncthreads();
            load_gi1(rr, 0, t, sh_i, sh_bh, 1, rbase, g, tg2, wc);
            if (doH) run_f16(rr, sh_ha + rbase*HP_, sh_W, lane, wc);
#pragma unroll
            for (int mt=0; mt<2; mt++)
#pragma unroll
                for (int nt=0; nt<4; nt++)
#pragma unroll
                    for (int q=0; q<4; q++) rr[mt][nt][q] = sigf(rr[mt][nt][q]);

            // gate n
            __syncthreads();
            if (doH) { stage1(sWu, g_W1 + 2*16384, tid); cp_wait_all(); }
            __syncthreads();
            float acci[2][4][4], acch[2][4][4];
            load_gi1(acci, 2, t, sh_i, nullptr, 0, rbase, g, tg2, wc);
#pragma unroll
            for (int mt=0; mt<2; mt++)
#pragma unroll
                for (int nt=0; nt<4; nt++) {
                    int cc = 2*F_ + wc*32 + nt*8 + tg2;
                    float2 bh = *(const float2*)&sh_bh[cc];
                    acch[mt][nt][0]=bh.x; acch[mt][nt][1]=bh.y;
                    acch[mt][nt][2]=bh.x; acch[mt][nt][3]=bh.y;
                }
            if (doH) run_f16(acch, sh_ha + rbase*HP_, sh_W, lane, wc);
#pragma unroll
            for (int mt=0; mt<2; mt++)
#pragma unroll
                for (int nt=0; nt<4; nt++)
#pragma unroll
                    for (int q=0; q<4; q++)
                        nn[mt][nt][q] = tanh_s(acci[mt][nt][q] + rr[mt][nt][q]*acch[mt][nt][q]);
        }

        // gate z
        float zz[2][4][4];
        __syncthreads();
        if (doH) { stage1(sWu, g_W1 + 1*16384, tid); cp_wait_all(); }
        __syncthreads();
        load_gi1(zz, 1, t, sh_i, sh_bh, 1, rbase, g, tg2, wc);
        if (doH) run_f16(zz, sh_ha + rbase*HP_, sh_W, lane, wc);
#pragma unroll
        for (int mt=0; mt<2; mt++)
#pragma unroll
            for (int nt=0; nt<4; nt++)
#pragma unroll
                for (int q=0; q<4; q++) zz[mt][nt][q] = sigf(zz[mt][nt][q]);

        __syncthreads();   // all GEMM reads of sh_ha complete
#pragma unroll
        for (int mt=0; mt<2; mt++)
#pragma unroll
            for (int nt=0; nt<4; nt++) {
                int cc = wc*32 + nt*8 + tg2;
#pragma unroll
                for (int p2=0; p2<2; p2++) {
                    int r = rbase + mt*16 + g + p2*8;
                    float n0 = nn[mt][nt][p2*2], n1 = nn[mt][nt][p2*2+1];
                    float z0 = zz[mt][nt][p2*2], z1 = zz[mt][nt][p2*2+1];
                    float2 ho = *(const float2*)&sh_hf[r*FP_ + cc];
                    float h0 = (1.f - z0)*n0 + z0*ho.x;
                    float h1 = (1.f - z1)*n1 + z1*ho.y;
                    *(float2*)&sh_hf[r*FP_ + cc] = make_float2(h0, h1);
                    __half2 hv = __floats2half2_rn(h0, h1);
                    *(__half2*)&sh_ha[r*HP_ + cc] = hv;
                    *(__half2*)&g_ywH[((size_t)t*SEQ_ + m0 + r)*F_ + cc] = hv;
                }
            }
    }
}

// ---------------- GRU2: fp16 single-pass, 2 blocks/SM ----------------
__device__ __forceinline__ void gate_gemm(float (&ax)[2][4][4], float (&ah2)[2][4][4], int jg,
    const __half* sh_x, const __half* sh_ha, uint32_t sWu, const __half* sh_W,
    int tid, int lane, int wc, int rbase)
{
    stage1(sWu, g_WX + (size_t)jg*16384, tid);
    cp_wait_all(); __syncthreads();
    run_f16(ax, sh_x + rbase*HP_, sh_W, lane, wc);
    __syncthreads();
    stage1(sWu, g_W2 + (size_t)jg*16384, tid);
    cp_wait_all(); __syncthreads();
    run_f16(ah2, sh_ha + rbase*HP_, sh_W, lane, wc);
}

__global__ void __launch_bounds__(NT_, 2) gru2_kernel(const float* __restrict__ bhh,
                                                      float* __restrict__ hT_out)
{
    extern __shared__ char smc[];
    float*  sh_hf = (float*)smc;                         // 33792
    __half* sh_ha = (__half*)(smc + 33792);              // 17408
    __half* sh_x  = (__half*)(smc + 33792 + 17408);      // 17408
    __half* sh_W  = (__half*)(smc + 33792 + 17408*2);    // 34816
    float*  sh_bh = (float*)(smc + 33792 + 17408*2 + 34816);
    int*    sh_i  = (int*)(smc + 33792 + 17408*2 + 34816 + 1536);

    const int tid = threadIdx.x, wid = tid >> 5, lane = tid & 31;
    const int wr = wid & 1, wc = wid >> 1;
    const int g = lane >> 2, tg2 = (lane & 3)*2;
    const int rbase = wr*32;
    const int m0 = blockIdx.x*MB_;
    const uint32_t sWu = (uint32_t)__cvta_generic_to_shared(sh_W);

    for (int i = tid; i < G3_; i += NT_) sh_bh[i] = bhh[i];
    for (int i = tid; i < MB_*F_; i += NT_) {
        int row = i >> 7, k = i & 127;
        __half v = g_ywH[((size_t)(L_-1)*SEQ_ + m0 + row)*F_ + k];
        sh_ha[row*HP_ + k] = v;
        sh_hf[row*FP_ + k] = __half2float(v);
    }

#pragma unroll 1
    for (int t = 0; t < L_; t++) {
        __syncthreads();   // prior step reads done
#pragma unroll
        for (int it = 0; it < 4; it++) {
            int i = tid + it*NT_;
            int row = i >> 4, seg = (i & 15) << 3;
            *(uint4*)(sh_x + row*HP_ + seg) =
                *(const uint4*)(g_ywH + ((size_t)t*SEQ_ + m0 + row)*F_ + seg);
        }
        if (tid < MB_) sh_i[tid] = g_walksf[(size_t)(m0 + tid)*L_ + t];
        __syncthreads();   // sh_x / sh_i visible

        float nn[2][4][4];
        {
            // gate r
            float rr[2][4][4];
            load_gi2(rr, 0, sh_i, sh_bh, 1, rbase, g, tg2, wc);
            gate_gemm(rr, rr, 0, sh_x, sh_ha, sWu, sh_W, tid, lane, wc, rbase);
#pragma unroll
            for (int mt=0; mt<2; mt++)
#pragma unroll
                for (int nt=0; nt<4; nt++)
#pragma unroll
                    for (int q=0; q<4; q++) rr[mt][nt][q] = sigf(rr[mt][nt][q]);

            // gate n
            __syncthreads();
            float acci[2][4][4], acch[2][4][4];
            load_gi2(acci, 2, sh_i, nullptr, 0, rbase, g, tg2, wc);
#pragma unroll
            for (int mt=0; mt<2; mt++)
#pragma unroll
                for (int nt=0; nt<4; nt++) {
                    int cc = 2*F_ + wc*32 + nt*8 + tg2;
                    float2 bh = *(const float2*)&sh_bh[cc];
                    acch[mt][nt][0]=bh.x; acch[mt][nt][1]=bh.y;
                    acch[mt][nt][2]=bh.x; acch[mt][nt][3]=bh.y;
                }
            gate_gemm(acci, acch, 2, sh_x, sh_ha, sWu, sh_W, tid, lane, wc, rbase);
#pragma unroll
            for (int mt=0; mt<2; mt++)
#pragma unroll
                for (int nt=0; nt<4; nt++)
#pragma unroll
                    for (int q=0; q<4; q++)
                        nn[mt][nt][q] = tanh_s(acci[mt][nt][q] + rr[mt][nt][q]*acch[mt][nt][q]);
        }

        // gate z
        float zz[2][4][4];
        __syncthreads();
        load_gi2(zz, 1, sh_i, sh_bh, 1, rbase, g, tg2, wc);
        gate_gemm(zz, zz, 1, sh_x, sh_ha, sWu, sh_W, tid, lane, wc, rbase);
#pragma unroll
        for (int mt=0; mt<2; mt++)
#pragma unroll
            for (int nt=0; nt<4; nt++)
#pragma unroll
                for (int q=0; q<4; q++) zz[mt][nt][q] = sigf(zz[mt][nt][q]);

        __syncthreads();   // all GEMM reads of sh_ha complete
#pragma unroll
        for (int mt=0; mt<2; mt++)
#pragma unroll
            for (int nt=0; nt<4; nt++) {
                int cc = wc*32 + nt*8 + tg2;
#pragma unroll
                for (int p2=0; p2<2; p2++) {
                    int r = rbase + mt*16 + g + p2*8;
                    float n0 = nn[mt][nt][p2*2], n1 = nn[mt][nt][p2*2+1];
                    float z0 = zz[mt][nt][p2*2], z1 = zz[mt][nt][p2*2+1];
                    float2 ho = *(const float2*)&sh_hf[r*FP_ + cc];
                    float h0 = (1.f - z0)*n0 + z0*ho.x;
                    float h1 = (1.f - z1)*n1 + z1*ho.y;
                    *(float2*)&sh_hf[r*FP_ + cc] = make_float2(h0, h1);
                    *(__half2*)&sh_ha[r*HP_ + cc] = __floats2half2_rn(h0, h1);
                    float* dst = (t < L_-1) ? (g_yseq[t] + ((size_t)(m0+r))*F_ + cc)
                                            : (hT_out   + ((size_t)(m0+r))*F_ + cc);
                    *(float2*)dst = make_float2(h0, h1);
                }
            }
    }
}

// ---------------- loss ----------------
__global__ void lsum_kernel(const int* __restrict__ idxs, const float* __restrict__ y0)
{
    int b = blockIdx.x;
    int t = b % (L_-1), j = (b/(L_-1)) % SUB_, s = b/((L_-1)*SUB_);
    int seq = s*N_ + idxs[j];
    int node = g_walksf[(size_t)seq*L_ + t + 1];
    int o = threadIdx.x;
    __shared__ float red[OR_];
    red[o] = y0[(size_t)node*OR_ + o]; __syncthreads();
    for (int st = OR_/2; st > 0; st >>= 1) { if (o < st) red[o] += red[o+st]; __syncthreads(); }
    if (o == 0) g_part1[b] = red[0];
}

__global__ void lred1_kernel()
{
    __shared__ float red[256];
    int tid = threadIdx.x; float s = 0.f;
    for (int i = tid; i < NB_LOSS; i += 256) s += g_part1[i];
    red[tid] = s; __syncthreads();
    for (int st = 128; st > 0; st >>= 1) { if (tid < st) red[tid] += red[tid+st]; __syncthreads(); }
    if (tid == 0) g_posw = LOSS_CNT / red[0];
}

__global__ void lbce_kernel(const int* __restrict__ idxs, const float* __restrict__ y0,
                            const float* __restrict__ Wss, const float* __restrict__ bss)
{
    int b = blockIdx.x;
    int t = b % (L_-1), j = (b/(L_-1)) % SUB_, s = b/((L_-1)*SUB_);
    int seq = s*N_ + idxs[j];
    __shared__ float yrow[F_];
    int o = threadIdx.x;
    yrow[o]      = g_yseq[t][(size_t)seq*F_ + o];
    yrow[o + 64] = g_yseq[t][(size_t)seq*F_ + o + 64];
    __syncthreads();
    float acc = bss[o];
    const float4* wrp = (const float4*)(Wss + (size_t)o*F_);
#pragma unroll 8
    for (int k = 0; k < F_/4; k++) {
        float4 w = wrp[k];
        acc += yrow[k*4]*w.x + yrow[k*4+1]*w.y + yrow[k*4+2]*w.z + yrow[k*4+3]*w.w;
    }
    int node = g_walksf[(size_t)seq*L_ + t + 1];
    float yt = y0[(size_t)node*OR_ + o];
    float term = g_posw * yt * softplusf(-acc) + (1.f - yt) * softplusf(acc);
    __shared__ float red[OR_];
    red[o] = term; __syncthreads();
    for (int st = OR_/2; st > 0; st >>= 1) { if (o < st) red[o] += red[o+st]; __syncthreads(); }
    if (o == 0) g_part2[b] = red[0];
}

__global__ void lred2_kernel(float* __restrict__ dst)
{
    __shared__ float red[256];
    int tid = threadIdx.x; float s = 0.f;
    for (int i = tid; i < NB_LOSS; i += 256) s += g_part2[i];
    red[tid] = s; __syncthreads();
    for (int st = 128; st > 0; st >>= 1) { if (tid < st) red[tid] += red[tid+st]; __syncthreads(); }
    if (tid == 0) *dst = red[0] / LOSS_CNT;
}

// ---------------- launch ----------------
extern "C" void kernel_launch(void* const* d_in, const int* in_sizes, int n_in,
                              void* d_out, int out_size)
{
    const float* h     = (const float*)d_in[0];
    const float* y0    = (const float*)d_in[1];
    const float* Wih_w = (const float*)d_in[2];
    const float* Whh_w = (const float*)d_in[3];
    const float* bih_w = (const float*)d_in[4];
    const float* bhh_w = (const float*)d_in[5];
    const float* Wih   = (const float*)d_in[6];
    const float* Whh   = (const float*)d_in[7];
    const float* bih   = (const float*)d_in[8];
    const float* bhh   = (const float*)d_in[9];
    const float* W_ss  = (const float*)d_in[10];
    const float* b_ss  = (const float*)d_in[11];
    const int*   walks = (const int*)d_in[12];
    const int*   idxs  = (const int*)d_in[13];
    float* out = (float*)d_out;

    const int SMEM_PT = 17408 + 34816;                       // 52224
    const int SMEM_G1 = 33792 + 17408 + 34816 + 1536 + 256;  // 87808
    const int SMEM_G2 = 33792 + 17408*2 + 34816 + 1536 + 256; // 105216
    cudaFuncSetAttribute(pT_kernel,   cudaFuncAttributeMaxDynamicSharedMemorySize, SMEM_PT);
    cudaFuncSetAttribute(gru1_kernel, cudaFuncAttributeMaxDynamicSharedMemorySize, SMEM_G1);
    cudaFuncSetAttribute(gru2_kernel, cudaFuncAttributeMaxDynamicSharedMemorySize, SMEM_G2);

    prep_kernel<<<(SEQ_ + 255)/256, 256>>>(walks);
    wg_kernel<<<1, G3_>>>(Wih_w, bih_w);
    pack_kernel<<<(G3_*F_ + 255)/256, 256>>>(Whh_w, Whh, Wih);
    packh_kernel<<<(NP_*F_ + 255)/256, 256>>>(h);
    pT_kernel<<<dim3(PTILES_, 3), NT_, SMEM_PT>>>(bih);
    gru1_kernel<<<TILES_, NT_, SMEM_G1>>>(bhh_w);
    gru2_kernel<<<TILES_, NT_, SMEM_G2>>>(bhh, out);
    lsum_kernel<<<NB_LOSS, OR_>>>(idxs, y0);
    lred1_kernel<<<1, 256>>>();
    lbce_kernel<<<NB_LOSS, OR_>>>(idxs, y0, W_ss, b_ss);
    lred2_kernel<<<1, 256>>>(out + (out_size - 1));
}